// round 4
// baseline (speedup 1.0000x reference)
#include <cuda_runtime.h>
#include <cuda_bf16.h>
#include <math.h>

// Problem constants
#define D_MODEL 768
#define N_HEADS 12
#define DH 64
#define BATCH 8
#define SEQ 256
#define NLAYER 6
#define MROWS (BATCH * SEQ)          // 2048
#define DFF (4 * D_MODEL)            // 3072
#define MD ((size_t)MROWS * D_MODEL) // 2048*768

// ---------------- scratch (device globals; no runtime allocation) ----------------
__device__ float g_x[MROWS * D_MODEL];
__device__ float g_y[MROWS * D_MODEL];
__device__ float g_qkv[3 * MROWS * D_MODEL];
__device__ float g_tmp[MROWS * D_MODEL];     // attention out / ffn2 out
__device__ float g_ffn[MROWS * DFF];         // ffn hidden

// ---------------- SGEMM: C[z] = act(A @ W[z] + bias[z]) ----------------
// BM=BN=64, BK=16, 256 threads, 4x4 per thread. A0 used for z==0, A1 for z>0
// (lets one launch do fused QKV where q comes from a different tensor than k,v).
__device__ __forceinline__ float gelu_exact(float x) {
    return 0.5f * x * (1.0f + erff(x * 0.70710678118654752f));
}

template<int ACT>
__global__ __launch_bounds__(256) void sgemm_kernel(
    const float* __restrict__ A0, const float* __restrict__ A1,
    const float* __restrict__ W, const float* __restrict__ bias,
    float* __restrict__ C, int N, int K,
    int wStrideZ, int biasStrideZ, size_t cStrideZ)
{
    const int z = blockIdx.z;
    const float* __restrict__ A = (z == 0) ? A0 : A1;
    W += (size_t)z * wStrideZ;
    bias += (size_t)z * biasStrideZ;
    C += (size_t)z * cStrideZ;

    __shared__ float As[16][68];   // transposed A tile, padded
    __shared__ float Bs[16][64];

    const int t  = threadIdx.x;
    const int ty = t >> 4;         // 0..15
    const int tx = t & 15;         // 0..15
    const int rowBase = blockIdx.y * 64;
    const int colBase = blockIdx.x * 64;

    const int aRow = t >> 2;          // 0..63
    const int aK   = (t & 3) * 4;     // 0,4,8,12

    float acc[4][4];
#pragma unroll
    for (int i = 0; i < 4; i++)
#pragma unroll
        for (int j = 0; j < 4; j++) acc[i][j] = 0.0f;

    for (int kt = 0; kt < K; kt += 16) {
        float4 av = *(const float4*)(A + (size_t)(rowBase + aRow) * K + kt + aK);
        float4 bv = *(const float4*)(W + (size_t)(kt + ty) * N + colBase + tx * 4);
        __syncthreads();
        As[aK + 0][aRow] = av.x;
        As[aK + 1][aRow] = av.y;
        As[aK + 2][aRow] = av.z;
        As[aK + 3][aRow] = av.w;
        *(float4*)&Bs[ty][tx * 4] = bv;
        __syncthreads();
#pragma unroll
        for (int k = 0; k < 16; k++) {
            float4 a = *(const float4*)&As[k][ty * 4];
            float4 b = *(const float4*)&Bs[k][tx * 4];
            acc[0][0] += a.x * b.x; acc[0][1] += a.x * b.y; acc[0][2] += a.x * b.z; acc[0][3] += a.x * b.w;
            acc[1][0] += a.y * b.x; acc[1][1] += a.y * b.y; acc[1][2] += a.y * b.z; acc[1][3] += a.y * b.w;
            acc[2][0] += a.z * b.x; acc[2][1] += a.z * b.y; acc[2][2] += a.z * b.z; acc[2][3] += a.z * b.w;
            acc[3][0] += a.w * b.x; acc[3][1] += a.w * b.y; acc[3][2] += a.w * b.z; acc[3][3] += a.w * b.w;
        }
    }

    float4 bb = *(const float4*)(bias + colBase + tx * 4);
#pragma unroll
    for (int i = 0; i < 4; i++) {
        int row = rowBase + ty * 4 + i;
        float4 o;
        o.x = acc[i][0] + bb.x;
        o.y = acc[i][1] + bb.y;
        o.z = acc[i][2] + bb.z;
        o.w = acc[i][3] + bb.w;
        if (ACT == 1) {
            o.x = gelu_exact(o.x); o.y = gelu_exact(o.y);
            o.z = gelu_exact(o.z); o.w = gelu_exact(o.w);
        }
        *(float4*)(C + (size_t)row * N + colBase + tx * 4) = o;
    }
}

// ---------------- fused attention (softmax(QK^T*scale + maskbias) @ V) ----------------
// One block per (b,h). One thread per query row. K/V streamed in 64-row smem chunks.
__global__ __launch_bounds__(256) void attn_kernel(
    const float* __restrict__ qb, const float* __restrict__ kb,
    const float* __restrict__ vb, const int* __restrict__ mask,
    float* __restrict__ out)
{
    const int bh = blockIdx.x;
    const int b = bh / N_HEADS;
    const int h = bh % N_HEADS;
    const int t = threadIdx.x;

    __shared__ float Ks[64 * 64];
    __shared__ float Vs[64 * 64];
    __shared__ float mb[SEQ];

    mb[t] = -10000.0f * (1.0f - (float)mask[b * SEQ + t]);

    const size_t qoff = ((size_t)(b * SEQ + t)) * D_MODEL + h * DH;
    float4 q4[16];
    const float4* qp = (const float4*)(qb + qoff);
#pragma unroll
    for (int i = 0; i < 16; i++) q4[i] = qp[i];

    float4 acc[16];
#pragma unroll
    for (int i = 0; i < 16; i++) acc[i] = make_float4(0.f, 0.f, 0.f, 0.f);
    float m = -1e30f, l = 0.0f;

    for (int kc = 0; kc < 4; kc++) {
        __syncthreads();
#pragma unroll
        for (int it = 0; it < 4; it++) {
            int idx = t + it * 256;            // float4 index, 0..1023
            int r = idx >> 4;
            int c = idx & 15;
            size_t gof = ((size_t)(b * SEQ + kc * 64 + r)) * D_MODEL + h * DH + c * 4;
            ((float4*)Ks)[idx] = *(const float4*)(kb + gof);
            ((float4*)Vs)[idx] = *(const float4*)(vb + gof);
        }
        __syncthreads();

        for (int kk = 0; kk < 64; kk++) {
            const float4* Kr = (const float4*)(Ks + kk * 64);
            float dot = 0.0f;
#pragma unroll
            for (int i = 0; i < 16; i++) {
                dot += q4[i].x * Kr[i].x + q4[i].y * Kr[i].y
                     + q4[i].z * Kr[i].z + q4[i].w * Kr[i].w;
            }
            float s  = dot * 0.125f + mb[kc * 64 + kk];
            float nm = fmaxf(m, s);
            float corr = __expf(m - nm);
            float p    = __expf(s - nm);
            l = l * corr + p;
            const float4* Vr = (const float4*)(Vs + kk * 64);
#pragma unroll
            for (int i = 0; i < 16; i++) {
                acc[i].x = fmaf(acc[i].x, corr, p * Vr[i].x);
                acc[i].y = fmaf(acc[i].y, corr, p * Vr[i].y);
                acc[i].z = fmaf(acc[i].z, corr, p * Vr[i].z);
                acc[i].w = fmaf(acc[i].w, corr, p * Vr[i].w);
            }
            m = nm;
        }
    }

    float inv = 1.0f / l;
    float4* op = (float4*)(out + qoff);
#pragma unroll
    for (int i = 0; i < 16; i++)
        op[i] = make_float4(acc[i].x * inv, acc[i].y * inv, acc[i].z * inv, acc[i].w * inv);
}

// ---------------- residual add + LayerNorm (in-place into x) ----------------
__global__ __launch_bounds__(256) void add_ln_kernel(
    float* __restrict__ x, const float* __restrict__ r,
    const float* __restrict__ g, const float* __restrict__ b)
{
    const int row = blockIdx.x;
    const int t = threadIdx.x;
    const size_t base = (size_t)row * D_MODEL;

    float v[3];
    float s = 0.f, s2 = 0.f;
#pragma unroll
    for (int j = 0; j < 3; j++) {
        int i = t + j * 256;
        float val = x[base + i] + r[base + i];
        v[j] = val;
        s += val;
        s2 += val * val;
    }
    __shared__ float sh1[256], sh2[256];
    sh1[t] = s; sh2[t] = s2;
    __syncthreads();
    for (int o = 128; o > 0; o >>= 1) {
        if (t < o) { sh1[t] += sh1[t + o]; sh2[t] += sh2[t + o]; }
        __syncthreads();
    }
    float mean = sh1[0] * (1.0f / D_MODEL);
    float var  = sh2[0] * (1.0f / D_MODEL) - mean * mean;
    float rstd = rsqrtf(var + 1e-12f);
#pragma unroll
    for (int j = 0; j < 3; j++) {
        int i = t + j * 256;
        x[base + i] = (v[j] - mean) * rstd * g[i] + b[i];
    }
}

// ---------------- host orchestration ----------------
extern "C" void kernel_launch(void* const* d_in, const int* in_sizes, int n_in,
                              void* d_out, int out_size)
{
    (void)in_sizes; (void)n_in;
    const float* in_x    = (const float*)d_in[0];
    const float* in_y    = (const float*)d_in[1];
    const int*   x_mask  = (const int*)d_in[2];
    const int*   y_mask  = (const int*)d_in[3];
    const float* ax_w = (const float*)d_in[4];
    const float* ax_b = (const float*)d_in[5];
    const float* cx_w = (const float*)d_in[6];
    const float* cx_b = (const float*)d_in[7];
    const float* fx_w1 = (const float*)d_in[8];
    const float* fx_b1 = (const float*)d_in[9];
    const float* fx_w2 = (const float*)d_in[10];
    const float* fx_b2 = (const float*)d_in[11];
    const float* ay_w = (const float*)d_in[12];
    const float* ay_b = (const float*)d_in[13];
    const float* cy_w = (const float*)d_in[14];
    const float* cy_b = (const float*)d_in[15];
    const float* fy_w1 = (const float*)d_in[16];
    const float* fy_b1 = (const float*)d_in[17];
    const float* fy_w2 = (const float*)d_in[18];
    const float* fy_b2 = (const float*)d_in[19];
    const float* lnx_g = (const float*)d_in[20];
    const float* lnx_b = (const float*)d_in[21];
    const float* lny_g = (const float*)d_in[22];
    const float* lny_b = (const float*)d_in[23];
    float* out = (float*)d_out;
    (void)out_size;

    float *gx, *gy, *gqkv, *gtmp, *gffn;
    cudaGetSymbolAddress((void**)&gx,   g_x);
    cudaGetSymbolAddress((void**)&gy,   g_y);
    cudaGetSymbolAddress((void**)&gqkv, g_qkv);
    cudaGetSymbolAddress((void**)&gtmp, g_tmp);
    cudaGetSymbolAddress((void**)&gffn, g_ffn);

    cudaMemcpyAsync(gx, in_x, MD * sizeof(float), cudaMemcpyDeviceToDevice, 0);
    cudaMemcpyAsync(gy, in_y, MD * sizeof(float), cudaMemcpyDeviceToDevice, 0);

    const dim3 gridProj(D_MODEL / 64, MROWS / 64, 3);   // fused QKV
    const dim3 gridF1(DFF / 64, MROWS / 64, 1);
    const dim3 gridF2(D_MODEL / 64, MROWS / 64, 1);
    const int DD = D_MODEL * D_MODEL;

    // one attention sublayer: cur = LN(cur + attn(q=cur, kv=kvsrc))
    auto attn_block = [&](float* cur, const float* kvsrc,
                          const float* w, const float* bb,
                          const int* mask, const float* lg, const float* lb) {
        sgemm_kernel<0><<<gridProj, 256>>>(cur, kvsrc, w, bb, gqkv,
                                           D_MODEL, D_MODEL, DD, D_MODEL, MD);
        attn_kernel<<<BATCH * N_HEADS, 256>>>(gqkv, gqkv + MD, gqkv + 2 * MD, mask, gtmp);
        add_ln_kernel<<<MROWS, 256>>>(cur, gtmp, lg, lb);
    };
    // one FFN sublayer: cur = LN(cur + W2(gelu(W1 cur + b1)) + b2)
    auto ffn_block = [&](float* cur, const float* w1, const float* b1,
                         const float* w2, const float* b2,
                         const float* lg, const float* lb) {
        sgemm_kernel<1><<<gridF1, 256>>>(cur, cur, w1, b1, gffn,
                                         DFF, D_MODEL, 0, 0, 0);
        sgemm_kernel<0><<<gridF2, 256>>>(gffn, gffn, w2, b2, gtmp,
                                         D_MODEL, DFF, 0, 0, 0);
        add_ln_kernel<<<MROWS, 256>>>(cur, gtmp, lg, lb);
    };

    for (int L = 0; L < NLAYER; L++) {
        const size_t wOff = (size_t)L * 3 * DD;
        const size_t bOff = (size_t)L * 3 * D_MODEL;
        // 1) x self-attention
        attn_block(gx, gx, ax_w + wOff, ax_b + bOff, x_mask, lnx_g + 0 * D_MODEL, lnx_b + 0 * D_MODEL);
        // 2) y self-attention
        attn_block(gy, gy, ay_w + wOff, ay_b + bOff, y_mask, lny_g + 0 * D_MODEL, lny_b + 0 * D_MODEL);
        // 3) x cross-attention (q from x, kv from updated y)
        attn_block(gx, gy, cx_w + wOff, cx_b + bOff, y_mask, lnx_g + 1 * D_MODEL, lnx_b + 1 * D_MODEL);
        // 4) y cross-attention (q from y, kv from updated x)
        attn_block(gy, gx, cy_w + wOff, cy_b + bOff, x_mask, lny_g + 1 * D_MODEL, lny_b + 1 * D_MODEL);
        // 5) x FFN
        ffn_block(gx, fx_w1 + (size_t)L * D_MODEL * DFF, fx_b1 + (size_t)L * DFF,
                      fx_w2 + (size_t)L * DFF * D_MODEL, fx_b2 + (size_t)L * D_MODEL,
                      lnx_g + 2 * D_MODEL, lnx_b + 2 * D_MODEL);
        // 6) y FFN
        ffn_block(gy, fy_w1 + (size_t)L * D_MODEL * DFF, fy_b1 + (size_t)L * DFF,
                      fy_w2 + (size_t)L * DFF * D_MODEL, fy_b2 + (size_t)L * D_MODEL,
                      lny_g + 2 * D_MODEL, lny_b + 2 * D_MODEL);
    }

    cudaMemcpyAsync(out,      gx, MD * sizeof(float), cudaMemcpyDeviceToDevice, 0);
    cudaMemcpyAsync(out + MD, gy, MD * sizeof(float), cudaMemcpyDeviceToDevice, 0);
}